// round 4
// baseline (speedup 1.0000x reference)
#include <cuda_runtime.h>
#include <math.h>

#define PI_D 3.14159265358979323846
#define SQH 0.70710678118654752440f

// ---------------- static device scratch ----------------
__device__ float2 g_S[512 * 2 * 128 * 128];   // state [b][f][X][Y]
__device__ float4 g_U0[128 * 128 * 2];        // mux0 unitaries, bitrev-permuted
__device__ float4 g_U1[2 * 2 * 64 * 64 * 2];
__device__ float4 g_U2[2 * 2 * 32 * 32 * 2];
__device__ float2 g_TW[64];                   // exp(-2*pi*i*t/128)
__device__ int    g_NR[128];                  // bitrev-domain negation table
__device__ float  g_part[512 * 2 * 10];       // partial logits per (b, xc1)

__device__ __forceinline__ float2 cmul(float2 a, float2 b) {
    return make_float2(a.x * b.x - a.y * b.y, a.x * b.y + a.y * b.x);
}
__device__ __forceinline__ float2 cmulc(float2 a, float2 b) {  // a * conj(b)
    return make_float2(a.x * b.x + a.y * b.y, a.y * b.x - a.x * b.y);
}
__device__ __forceinline__ float2 f2add(float2 a, float2 b) { return make_float2(a.x + b.x, a.y + b.y); }
__device__ __forceinline__ float2 f2sub(float2 a, float2 b) { return make_float2(a.x - b.x, a.y - b.y); }
__device__ __forceinline__ float2 f2sc(float2 a, float s) { return make_float2(a.x * s, a.y * s); }
__device__ __forceinline__ float2 csq(float2 a) { return make_float2(a.x * a.x - a.y * a.y, 2.f * a.x * a.y); }

// =====================================================================
// FFT passes. element (line, p) at base[(line&(2^LG1-1))*SL1 + (line>>LG1)*SL2 + p*SP]
// FWD: DIF natural->bitrev, tw exp(-2pi i q/2H) on diff. INV: DIT bitrev->natural,
// conj twiddles on b before add/sub. Scale folded into last INV pass.
// =====================================================================

// radix-8 pass: three radix-2 stages {S+2, S+1, S} (FWD) / {S, S+1, S+2} (INV)
template<bool INV, int NTT, int SP, int SL1, int LG1, int SL2, int LG2, int LOGN, int S, bool LAST>
__device__ __forceinline__ void pass8(float2* __restrict__ base,
                                      const float2* __restrict__ tw, float scale) {
    constexpr int L = 1 << (LG1 + LG2);
    constexpr int ITEMS = L << (LOGN - 3);
    constexpr int h = 1 << S;
    #pragma unroll 1
    for (int u = threadIdx.x; u < ITEMS; u += NTT) {
        const int line = u & (L - 1);
        const int loff = (line & ((1 << LG1) - 1)) * SL1 + (line >> LG1) * SL2;
        const int v = u >> (LG1 + LG2);
        const int t = v & (h - 1);
        const int p = ((v >> S) << (S + 3)) + t;
        float2* e = base + loff + p * SP;
        float2 d0 = e[0],          d1 = e[h * SP],     d2 = e[2 * h * SP], d3 = e[3 * h * SP];
        float2 d4 = e[4 * h * SP], d5 = e[5 * h * SP], d6 = e[6 * h * SP], d7 = e[7 * h * SP];
        const float2 w  = tw[t << (4 - S)];                         // W(t, 8h)
        const float2 w1 = make_float2(SQH * (w.x + w.y), SQH * (w.y - w.x));   // w*e^{-i pi/4}
        const float2 w2 = make_float2(w.y, -w.x);                              // w*(-i)
        const float2 w3 = make_float2(SQH * (w.y - w.x), -SQH * (w.x + w.y));  // w*e^{-3i pi/4}
        const float2 u2  = csq(w);                                  // W(t, 4h)
        const float2 u2m = make_float2(u2.y, -u2.x);                // W(t+h, 4h)
        const float2 v4  = csq(u2);                                 // W(t, 2h)
        if constexpr (!INV) {
            float2 s0 = f2add(d0, d4), s1 = f2add(d1, d5), s2 = f2add(d2, d6), s3 = f2add(d3, d7);
            float2 t0 = cmul(f2sub(d0, d4), w);
            float2 t1 = cmul(f2sub(d1, d5), w1);
            float2 t2 = cmul(f2sub(d2, d6), w2);
            float2 t3 = cmul(f2sub(d3, d7), w3);
            float2 a0 = f2add(s0, s2), a2 = cmul(f2sub(s0, s2), u2);
            float2 a1 = f2add(s1, s3), a3 = cmul(f2sub(s1, s3), u2m);
            float2 b0 = f2add(t0, t2), b2 = cmul(f2sub(t0, t2), u2);
            float2 b1 = f2add(t1, t3), b3 = cmul(f2sub(t1, t3), u2m);
            e[0]          = f2add(a0, a1);  e[h * SP]     = cmul(f2sub(a0, a1), v4);
            e[2 * h * SP] = f2add(a2, a3);  e[3 * h * SP] = cmul(f2sub(a2, a3), v4);
            e[4 * h * SP] = f2add(b0, b1);  e[5 * h * SP] = cmul(f2sub(b0, b1), v4);
            e[6 * h * SP] = f2add(b2, b3);  e[7 * h * SP] = cmul(f2sub(b2, b3), v4);
        } else {
            float2 q1 = cmulc(d1, v4), q3 = cmulc(d3, v4), q5 = cmulc(d5, v4), q7 = cmulc(d7, v4);
            float2 c0 = f2add(d0, q1), c1 = f2sub(d0, q1);
            float2 c2 = f2add(d2, q3), c3 = f2sub(d2, q3);
            float2 c4 = f2add(d4, q5), c5 = f2sub(d4, q5);
            float2 c6 = f2add(d6, q7), c7 = f2sub(d6, q7);
            float2 r2 = cmulc(c2, u2), r3 = cmulc(c3, u2m), r6 = cmulc(c6, u2), r7 = cmulc(c7, u2m);
            float2 g0 = f2add(c0, r2), g2 = f2sub(c0, r2);
            float2 g1 = f2add(c1, r3), g3 = f2sub(c1, r3);
            float2 g4 = f2add(c4, r6), g6 = f2sub(c4, r6);
            float2 g5 = f2add(c5, r7), g7 = f2sub(c5, r7);
            float2 h4 = cmulc(g4, w), h5 = cmulc(g5, w1), h6 = cmulc(g6, w2), h7 = cmulc(g7, w3);
            float2 o0 = f2add(g0, h4), o4 = f2sub(g0, h4);
            float2 o1 = f2add(g1, h5), o5 = f2sub(g1, h5);
            float2 o2 = f2add(g2, h6), o6 = f2sub(g2, h6);
            float2 o3 = f2add(g3, h7), o7 = f2sub(g3, h7);
            if constexpr (LAST) {
                o0 = f2sc(o0, scale); o1 = f2sc(o1, scale); o2 = f2sc(o2, scale); o3 = f2sc(o3, scale);
                o4 = f2sc(o4, scale); o5 = f2sc(o5, scale); o6 = f2sc(o6, scale); o7 = f2sc(o7, scale);
            }
            e[0]          = o0; e[h * SP]     = o1; e[2 * h * SP] = o2; e[3 * h * SP] = o3;
            e[4 * h * SP] = o4; e[5 * h * SP] = o5; e[6 * h * SP] = o6; e[7 * h * SP] = o7;
        }
    }
    __syncthreads();
}

// radix-4 pass: stages {S+1, S} (FWD) / {S, S+1} (INV)
template<bool INV, int NTT, int SP, int SL1, int LG1, int SL2, int LG2, int LOGN, int S, bool LAST>
__device__ __forceinline__ void pass4(float2* __restrict__ base,
                                      const float2* __restrict__ tw, float scale) {
    constexpr int L = 1 << (LG1 + LG2);
    constexpr int ITEMS = L << (LOGN - 2);
    constexpr int h = 1 << S;
    #pragma unroll 1
    for (int u = threadIdx.x; u < ITEMS; u += NTT) {
        const int line = u & (L - 1);
        const int loff = (line & ((1 << LG1) - 1)) * SL1 + (line >> LG1) * SL2;
        const int v = u >> (LG1 + LG2);
        const int t = v & (h - 1);
        const int p = ((v >> S) << (S + 2)) + t;
        float2* e = base + loff + p * SP;
        float2 a = e[0], b = e[h * SP], c = e[2 * h * SP], d = e[3 * h * SP];
        const float2 w0 = tw[t << (5 - S)];                 // W(t, 4h)
        const float2 w1 = make_float2(w0.y, -w0.x);         // W(t+h, 4h)
        const float2 w2 = csq(w0);                          // W(t, 2h)
        if constexpr (!INV) {
            float2 ac = f2add(a, c), bd = f2add(b, d);
            float2 cP = cmul(f2sub(a, c), w0);
            float2 dP = cmul(f2sub(b, d), w1);
            e[0]          = f2add(ac, bd);
            e[h * SP]     = cmul(f2sub(ac, bd), w2);
            e[2 * h * SP] = f2add(cP, dP);
            e[3 * h * SP] = cmul(f2sub(cP, dP), w2);
        } else {
            float2 bw = cmulc(b, w2), dw = cmulc(d, w2);
            float2 aP = f2add(a, bw), bP = f2sub(a, bw);
            float2 cP = f2add(c, dw), dP = f2sub(c, dw);
            float2 cw = cmulc(cP, w0), dq = cmulc(dP, w1);
            float2 o0 = f2add(aP, cw), o2 = f2sub(aP, cw);
            float2 o1 = f2add(bP, dq), o3 = f2sub(bP, dq);
            if constexpr (LAST) {
                o0 = f2sc(o0, scale); o1 = f2sc(o1, scale);
                o2 = f2sc(o2, scale); o3 = f2sc(o3, scale);
            }
            e[0] = o0; e[h * SP] = o1; e[2 * h * SP] = o2; e[3 * h * SP] = o3;
        }
    }
    __syncthreads();
}

// radix-2 pass: single stage S
template<bool INV, int NTT, int SP, int SL1, int LG1, int SL2, int LG2, int LOGN, int S, bool LAST>
__device__ __forceinline__ void pass2(float2* __restrict__ base,
                                      const float2* __restrict__ tw, float scale) {
    constexpr int L = 1 << (LG1 + LG2);
    constexpr int ITEMS = L << (LOGN - 1);
    constexpr int h = 1 << S;
    #pragma unroll 1
    for (int u = threadIdx.x; u < ITEMS; u += NTT) {
        const int line = u & (L - 1);
        const int loff = (line & ((1 << LG1) - 1)) * SL1 + (line >> LG1) * SL2;
        const int v = u >> (LG1 + LG2);
        const int t = v & (h - 1);
        const int p = ((v >> S) << (S + 1)) + t;
        float2* e = base + loff + p * SP;
        float2 a = e[0], b = e[h * SP];
        const float2 w = tw[t << (6 - S)];                  // W(t, 2h)
        if constexpr (!INV) {
            e[0]      = f2add(a, b);
            e[h * SP] = cmul(f2sub(a, b), w);
        } else {
            float2 bw = cmulc(b, w);
            float2 o0 = f2add(a, bw), o1 = f2sub(a, bw);
            if constexpr (LAST) { o0 = f2sc(o0, scale); o1 = f2sc(o1, scale); }
            e[0] = o0; e[h * SP] = o1;
        }
    }
    __syncthreads();
}

template<bool INV, int NTT, int SP, int SL1, int LG1, int SL2, int LG2, int LOGN>
__device__ __forceinline__ void fft_run(float2* __restrict__ base,
                                        const float2* __restrict__ tw, float scale) {
    if constexpr (!INV) {
        if constexpr (LOGN == 7) {
            pass8<false, NTT, SP, SL1, LG1, SL2, LG2, 7, 4, false>(base, tw, 1.f);
            pass8<false, NTT, SP, SL1, LG1, SL2, LG2, 7, 1, false>(base, tw, 1.f);
            pass2<false, NTT, SP, SL1, LG1, SL2, LG2, 7, 0, false>(base, tw, 1.f);
        } else if constexpr (LOGN == 6) {
            pass8<false, NTT, SP, SL1, LG1, SL2, LG2, 6, 3, false>(base, tw, 1.f);
            pass8<false, NTT, SP, SL1, LG1, SL2, LG2, 6, 0, false>(base, tw, 1.f);
        } else {
            pass8<false, NTT, SP, SL1, LG1, SL2, LG2, 5, 2, false>(base, tw, 1.f);
            pass4<false, NTT, SP, SL1, LG1, SL2, LG2, 5, 0, false>(base, tw, 1.f);
        }
    } else {
        if constexpr (LOGN == 7) {
            pass8<true, NTT, SP, SL1, LG1, SL2, LG2, 7, 0, false>(base, tw, 1.f);
            pass8<true, NTT, SP, SL1, LG1, SL2, LG2, 7, 3, false>(base, tw, 1.f);
            pass2<true, NTT, SP, SL1, LG1, SL2, LG2, 7, 6, true >(base, tw, scale);
        } else if constexpr (LOGN == 6) {
            pass8<true, NTT, SP, SL1, LG1, SL2, LG2, 6, 0, false>(base, tw, 1.f);
            pass8<true, NTT, SP, SL1, LG1, SL2, LG2, 6, 3, true >(base, tw, scale);
        } else {
            pass8<true, NTT, SP, SL1, LG1, SL2, LG2, 5, 0, false>(base, tw, 1.f);
            pass4<true, NTT, SP, SL1, LG1, SL2, LG2, 5, 3, true >(base, tw, scale);
        }
    }
}

__device__ __forceinline__ void apply_mux(float2& p0, float2& p1, float4 uA, float4 uB) {
    float2 o0, o1;
    o0.x = uA.x * p0.x - uA.y * p0.y + uA.z * p1.x - uA.w * p1.y;
    o0.y = uA.x * p0.y + uA.y * p0.x + uA.z * p1.y + uA.w * p1.x;
    o1.x = uB.x * p0.x - uB.y * p0.y + uB.z * p1.x - uB.w * p1.y;
    o1.y = uB.x * p0.y + uB.y * p0.x + uB.z * p1.y + uB.w * p1.x;
    p0 = o0; p1 = o1;
}

// ---------------- K0: precompute ----------------
__device__ __forceinline__ void writeU(float4* dst, float axf, float ayf, float azf) {
    double ax = axf, ay = ayf, az = azf;
    double r = sqrt(ax * ax + ay * ay + az * az + 1e-20);
    double cr = cos(r), sn = sin(r) / r;
    dst[0] = make_float4((float)cr, (float)(-az * sn), (float)(-ay * sn), (float)(-ax * sn));
    dst[1] = make_float4((float)(ay * sn), (float)(-ax * sn), (float)cr, (float)(az * sn));
}

__global__ void k0(const float* __restrict__ mux0, const float* __restrict__ mux1,
                   const float* __restrict__ mux2) {
    int idx = blockIdx.x * blockDim.x + threadIdx.x;   // 16384 threads
    if (idx < 64) {
        double ang = -2.0 * PI_D * (double)idx / 128.0;
        g_TW[idx] = make_float2((float)cos(ang), (float)sin(ang));
    }
    if (idx < 128) {
        int k = __brev((unsigned)idx) >> 25;
        g_NR[idx] = (int)(__brev((unsigned)((128 - k) & 127)) >> 25);
    }
    {
        int kxb = idx >> 7, kyb = idx & 127;
        int kx = __brev((unsigned)kxb) >> 25, ky = __brev((unsigned)kyb) >> 25;
        const float* c = mux0 + (kx * 128 + ky) * 3;
        writeU(&g_U0[idx * 2], c[0], c[1], c[2]);
    }
    {
        int cx = idx >> 13, cy = (idx >> 12) & 1, kxb = (idx >> 6) & 63, kyb = idx & 63;
        int kx = __brev((unsigned)kxb) >> 26, ky = __brev((unsigned)kyb) >> 26;
        const float* c = mux1 + (((cx * 2 + cy) * 64 + kx) * 64 + ky) * 3;
        writeU(&g_U1[idx * 2], c[0], c[1], c[2]);
    }
    if (idx < 4096) {
        int cx = idx >> 11, cy = (idx >> 10) & 1, kxb = (idx >> 5) & 31, kyb = idx & 31;
        int kx = __brev((unsigned)kxb) >> 27, ky = __brev((unsigned)kyb) >> 27;
        const float* c = mux2 + (((cx * 2 + cy) * 32 + kx) * 32 + ky) * 3;
        writeU(&g_U2[idx * 2], c[0], c[1], c[2]);
    }
}

// ---------------- P1: encode + y-FFT128 (Hermitian packed) ----------------
#define NT1 512
__global__ __launch_bounds__(NT1) void p1(const float* __restrict__ images) {
    __shared__ float2 z[128 * 33];
    __shared__ float2 tw[64];
    const int b = blockIdx.y, X0 = blockIdx.x * 32;
    for (int i = threadIdx.x; i < 64; i += NT1) tw[i] = g_TW[i];
    for (int idx = threadIdx.x; idx < 4096; idx += NT1) {
        int l = idx >> 7, y = idx & 127;
        float I = images[(b * 128 + X0 + l) * 128 + y];
        float sv, cv;
        sincosf(0.5f * (float)PI_D * I, &sv, &cv);
        z[y * 33 + l] = make_float2(cv * (1.0f / 128.0f), sv * (1.0f / 128.0f));
    }
    __syncthreads();
    fft_run<false, NT1, 33, 1, 5, 0, 0, 7>(z, tw, 1.f);
    for (int idx = threadIdx.x; idx < 4096; idx += NT1) {
        int l = idx >> 7, kb = idx & 127;
        float2 Z = z[kb * 33 + l];
        float2 Zn = z[g_NR[kb] * 33 + l];
        float2 C  = make_float2(0.5f * (Z.x + Zn.x), 0.5f * (Z.y - Zn.y));
        float2 Sf = make_float2(0.5f * (Z.y + Zn.y), 0.5f * (Zn.x - Z.x));
        int X = X0 + l;
        g_S[((b * 2 + 0) * 128 + X) * 128 + kb] = C;
        g_S[((b * 2 + 1) * 128 + X) * 128 + kb] = Sf;
    }
}

// ---------------- P2: x-FFT128 + mux0 + x-IFFT128 + x-FFT64(halves) ----------------
#define NT2 512
__global__ __launch_bounds__(NT2) void p2() {
    __shared__ float2 tile[2 * 128 * 16];
    __shared__ float2 tw[64];
    const int b = blockIdx.y, y0 = blockIdx.x * 16;
    for (int i = threadIdx.x; i < 64; i += NT2) tw[i] = g_TW[i];
    for (int idx = threadIdx.x; idx < 4096; idx += NT2) {
        int yl = idx & 15, X = (idx >> 4) & 127, f = idx >> 11;
        tile[f * 2048 + X * 16 + yl] = g_S[((b * 2 + f) * 128 + X) * 128 + y0 + yl];
    }
    __syncthreads();
    fft_run<false, NT2, 16, 1, 4, 2048, 1, 7>(tile, tw, 1.f);
    for (int idx = threadIdx.x; idx < 2048; idx += NT2) {
        int yl = idx & 15, kxb = idx >> 4;
        int off = kxb * 16 + yl;
        float2 q0 = tile[off], q1 = tile[2048 + off];
        int ui = ((kxb << 7) + y0 + yl) * 2;
        apply_mux(q0, q1, g_U0[ui], g_U0[ui + 1]);
        tile[off] = q0; tile[2048 + off] = q1;
    }
    __syncthreads();
    fft_run<true,  NT2, 16, 1, 4, 2048, 1, 7>(tile, tw, 1.0f / 128.0f);
    fft_run<false, NT2, 16, 1, 4, 1024, 2, 6>(tile, tw, 1.f);   // halves x planes
    for (int idx = threadIdx.x; idx < 4096; idx += NT2) {
        int yl = idx & 15, X = (idx >> 4) & 127, f = idx >> 11;
        g_S[((b * 2 + f) * 128 + X) * 128 + y0 + yl] = tile[f * 2048 + X * 16 + yl];
    }
}

// ---------------- P35: y-junction + mux1 + x-junction + y-junction + mux2
//                   + final IFFT32s + measure + partial GEMV ----------------
#define NT3 1024
#define P35_SMEM (132096 + 512 + 8192 + 1280)
__global__ __launch_bounds__(NT3) void p35(const float* __restrict__ W) {
    extern __shared__ char sm[];
    float2* tile = (float2*)sm;                            // [2][64][129]
    float2* tw   = (float2*)(sm + 132096);
    float*  prob = (float*)(sm + 132096 + 512);            // 2048 f32
    float*  red  = (float*)(sm + 132096 + 512 + 8192);     // 32*10 f32
    const int b = blockIdx.y, xc1 = blockIdx.x;
    for (int i = threadIdx.x; i < 64; i += NT3) tw[i] = g_TW[i];
    for (int idx = threadIdx.x; idx < 16384; idx += NT3) {
        int Y = idx & 127, X = (idx >> 7) & 63, f = idx >> 13;
        tile[f * 8256 + X * 129 + Y] = g_S[((b * 2 + f) * 128 + xc1 * 64 + X) * 128 + Y];
    }
    __syncthreads();
    // y junction 128->64
    fft_run<true,  NT3, 1, 129, 7, 0,  0, 7>(tile, tw, 1.0f / 128.0f);
    fft_run<false, NT3, 1, 129, 7, 64, 1, 6>(tile, tw, 1.f);
    // mux1
    for (int idx = threadIdx.x; idx < 8192; idx += NT3) {
        int Y = idx & 127, X = idx >> 7;
        int off = X * 129 + Y;
        float2 q0 = tile[off], q1 = tile[8256 + off];
        int yc1 = Y >> 6, Yb = Y & 63;
        int ui = (((xc1 * 2 + yc1) << 12) + (X << 6) + Yb) * 2;
        apply_mux(q0, q1, g_U1[ui], g_U1[ui + 1]);
        tile[off] = q0; tile[8256 + off] = q1;
    }
    __syncthreads();
    // x junction 64->32, then y junction 64->32
    fft_run<true,  NT3, 129, 1, 7, 8256, 1, 6>(tile, tw, 1.0f / 64.0f);
    fft_run<false, NT3, 129, 1, 7, 4128, 2, 5>(tile, tw, 1.f);
    fft_run<true,  NT3, 1, 129, 7, 64, 1, 6>(tile, tw, 1.0f / 64.0f);
    fft_run<false, NT3, 1, 129, 7, 32, 2, 5>(tile, tw, 1.f);
    // mux2
    for (int idx = threadIdx.x; idx < 8192; idx += NT3) {
        int Y = idx & 127, X = idx >> 7;
        int off = X * 129 + Y;
        float2 q0 = tile[off], q1 = tile[8256 + off];
        int xc2 = X >> 5, yc2 = (Y >> 5) & 1;
        int ui = (((xc2 * 2 + yc2) << 10) + ((X & 31) << 5) + (Y & 31)) * 2;
        apply_mux(q0, q1, g_U2[ui], g_U2[ui + 1]);
        tile[off] = q0; tile[8256 + off] = q1;
    }
    __syncthreads();
    // final iqft2d (32-point both axes)
    fft_run<true, NT3, 129, 1, 7, 4128, 2, 5>(tile, tw, 1.0f / 32.0f);
    fft_run<true, NT3, 1, 129, 7, 32,   2, 5>(tile, tw, 1.0f / 32.0f);
    // measurement: partial prob over (xc2, yc1, yc2)
    for (int idx = threadIdx.x; idx < 2048; idx += NT3) {
        int f = idx & 1, ya = (idx >> 1) & 31, xa = idx >> 6;
        float s = 0.f;
        #pragma unroll
        for (int xc2 = 0; xc2 < 2; ++xc2)
            #pragma unroll
            for (int yq = 0; yq < 4; ++yq) {
                float2 v = tile[f * 8256 + (xc2 * 32 + xa) * 129 + yq * 32 + ya];
                s += v.x * v.x + v.y * v.y;
            }
        prob[idx] = s;
    }
    __syncthreads();
    // partial GEMV
    float acc[10];
    #pragma unroll
    for (int c = 0; c < 10; ++c) acc[c] = 0.f;
    {
        int j0 = threadIdx.x * 2;
        float2 pv = *(const float2*)(prob + j0);
        #pragma unroll
        for (int c = 0; c < 10; ++c) {
            float2 wv = *(const float2*)(W + c * 2048 + j0);
            acc[c] = fmaf(pv.x, wv.x, fmaf(pv.y, wv.y, acc[c]));
        }
    }
    #pragma unroll
    for (int c = 0; c < 10; ++c)
        #pragma unroll
        for (int o = 16; o > 0; o >>= 1)
            acc[c] += __shfl_down_sync(0xffffffffu, acc[c], o);
    const int warp = threadIdx.x >> 5, lane = threadIdx.x & 31;
    if (lane == 0)
        #pragma unroll
        for (int c = 0; c < 10; ++c) red[warp * 10 + c] = acc[c];
    __syncthreads();
    if (threadIdx.x < 10) {
        float s = 0.f;
        #pragma unroll
        for (int w = 0; w < 32; ++w) s += red[w * 10 + threadIdx.x];
        g_part[(b * 2 + xc1) * 10 + threadIdx.x] = s;
    }
}

// ---------------- combine ----------------
__global__ void pc(const float* __restrict__ bias, float* __restrict__ out) {
    int i = blockIdx.x * blockDim.x + threadIdx.x;
    if (i < 5120) {
        int b = i / 10, c = i % 10;
        out[i] = bias[c] + g_part[(b * 2) * 10 + c] + g_part[(b * 2 + 1) * 10 + c];
    }
}

// ---------------- launch ----------------
extern "C" void kernel_launch(void* const* d_in, const int* in_sizes, int n_in,
                              void* d_out, int out_size) {
    const float* images = (const float*)d_in[0];
    const float* mux0 = (const float*)d_in[1];
    const float* mux1 = (const float*)d_in[2];
    const float* mux2 = (const float*)d_in[3];
    const float* W = (const float*)d_in[4];
    const float* bias = (const float*)d_in[5];
    float* out = (float*)d_out;
    (void)in_sizes; (void)n_in; (void)out_size;

    cudaFuncSetAttribute(p35, cudaFuncAttributeMaxDynamicSharedMemorySize, P35_SMEM);

    k0<<<64, 256>>>(mux0, mux1, mux2);
    p1<<<dim3(4, 512), NT1>>>(images);
    p2<<<dim3(8, 512), NT2>>>();
    p35<<<dim3(2, 512), NT3, P35_SMEM>>>(W);
    pc<<<10, 512>>>(bias, out);
}

// round 5
// speedup vs baseline: 1.1223x; 1.1223x over previous
#include <cuda_runtime.h>
#include <math.h>

#define PI_D 3.14159265358979323846

// ---------------- static device scratch ----------------
__device__ float2 g_S[512 * 2 * 128 * 128];   // state [b][f][X][Y]
__device__ float4 g_U0[128 * 128 * 2];        // mux0 unitaries, bitrev-permuted
__device__ float4 g_U1[2 * 2 * 64 * 64 * 2];
__device__ float4 g_U2[2 * 2 * 32 * 32 * 2];
__device__ float2 g_TW[64];                   // exp(-2*pi*i*t/128)
__device__ int    g_NR[128];                  // bitrev-domain negation table
__device__ float  g_part[512 * 2 * 10];       // partial logits per (b, xc1)

__device__ __forceinline__ float2 cmul(float2 a, float2 b) {
    return make_float2(a.x * b.x - a.y * b.y, a.x * b.y + a.y * b.x);
}
__device__ __forceinline__ float2 cmulc(float2 a, float2 b) {  // a * conj(b)
    return make_float2(a.x * b.x + a.y * b.y, a.y * b.x - a.x * b.y);
}
__device__ __forceinline__ float2 f2add(float2 a, float2 b) { return make_float2(a.x + b.x, a.y + b.y); }
__device__ __forceinline__ float2 f2sub(float2 a, float2 b) { return make_float2(a.x - b.x, a.y - b.y); }
__device__ __forceinline__ float2 f2sc(float2 a, float s) { return make_float2(a.x * s, a.y * s); }
__device__ __forceinline__ float2 csq(float2 a) { return make_float2(a.x * a.x - a.y * a.y, 2.f * a.x * a.y); }

// =====================================================================
// Pass-granular radix-4 / radix-2 smem FFT (R3-proven codegen; no unroll pragmas)
// element (line, p) at base[(line&(2^LG1-1))*SL1 + (line>>LG1)*SL2 + p*SP]
// FWD: DIF natural->bitrev; INV: DIT bitrev->natural (conj twiddles), scale on LAST.
// =====================================================================

// radix-4 pass: stages {S+1, S} (FWD) / {S, S+1} (INV)
template<bool INV, int NTT, int SP, int SL1, int LG1, int SL2, int LG2, int LOGN, int S, bool LAST>
__device__ __forceinline__ void pass4(float2* __restrict__ base,
                                      const float2* __restrict__ tw, float scale) {
    constexpr int L = 1 << (LG1 + LG2);
    constexpr int ITEMS = L << (LOGN - 2);
    constexpr int h = 1 << S;
    for (int u = threadIdx.x; u < ITEMS; u += NTT) {
        const int line = u & (L - 1);
        const int loff = (line & ((1 << LG1) - 1)) * SL1 + (line >> LG1) * SL2;
        const int v = u >> (LG1 + LG2);
        const int t = v & (h - 1);
        const int p = ((v >> S) << (S + 2)) + t;
        float2* e = base + loff + p * SP;
        float2 a = e[0], b = e[h * SP], c = e[2 * h * SP], d = e[3 * h * SP];
        const float2 w0 = tw[t << (5 - S)];                 // W(t, 4h)
        const float2 w1 = make_float2(w0.y, -w0.x);         // W(t+h, 4h)
        const float2 w2 = csq(w0);                          // W(t, 2h)
        if constexpr (!INV) {
            float2 ac = f2add(a, c), bd = f2add(b, d);
            float2 cP = cmul(f2sub(a, c), w0);
            float2 dP = cmul(f2sub(b, d), w1);
            e[0]          = f2add(ac, bd);
            e[h * SP]     = cmul(f2sub(ac, bd), w2);
            e[2 * h * SP] = f2add(cP, dP);
            e[3 * h * SP] = cmul(f2sub(cP, dP), w2);
        } else {
            float2 bw = cmulc(b, w2), dw = cmulc(d, w2);
            float2 aP = f2add(a, bw), bP = f2sub(a, bw);
            float2 cP = f2add(c, dw), dP = f2sub(c, dw);
            float2 cw = cmulc(cP, w0), dq = cmulc(dP, w1);
            float2 o0 = f2add(aP, cw), o2 = f2sub(aP, cw);
            float2 o1 = f2add(bP, dq), o3 = f2sub(bP, dq);
            if constexpr (LAST) {
                o0 = f2sc(o0, scale); o1 = f2sc(o1, scale);
                o2 = f2sc(o2, scale); o3 = f2sc(o3, scale);
            }
            e[0] = o0; e[h * SP] = o1; e[2 * h * SP] = o2; e[3 * h * SP] = o3;
        }
    }
    __syncthreads();
}

// radix-2 pass: single stage S
template<bool INV, int NTT, int SP, int SL1, int LG1, int SL2, int LG2, int LOGN, int S, bool LAST>
__device__ __forceinline__ void pass2(float2* __restrict__ base,
                                      const float2* __restrict__ tw, float scale) {
    constexpr int L = 1 << (LG1 + LG2);
    constexpr int ITEMS = L << (LOGN - 1);
    constexpr int h = 1 << S;
    for (int u = threadIdx.x; u < ITEMS; u += NTT) {
        const int line = u & (L - 1);
        const int loff = (line & ((1 << LG1) - 1)) * SL1 + (line >> LG1) * SL2;
        const int v = u >> (LG1 + LG2);
        const int t = v & (h - 1);
        const int p = ((v >> S) << (S + 1)) + t;
        float2* e = base + loff + p * SP;
        float2 a = e[0], b = e[h * SP];
        const float2 w = tw[t << (6 - S)];                  // W(t, 2h)
        if constexpr (!INV) {
            e[0]      = f2add(a, b);
            e[h * SP] = cmul(f2sub(a, b), w);
        } else {
            float2 bw = cmulc(b, w);
            float2 o0 = f2add(a, bw), o1 = f2sub(a, bw);
            if constexpr (LAST) { o0 = f2sc(o0, scale); o1 = f2sc(o1, scale); }
            e[0] = o0; e[h * SP] = o1;
        }
    }
    __syncthreads();
}

template<bool INV, int NTT, int SP, int SL1, int LG1, int SL2, int LG2, int LOGN>
__device__ __forceinline__ void fft_run(float2* __restrict__ base,
                                        const float2* __restrict__ tw, float scale) {
    if constexpr (!INV) {
        if constexpr (LOGN == 7) {
            pass4<false, NTT, SP, SL1, LG1, SL2, LG2, 7, 5, false>(base, tw, 1.f);
            pass4<false, NTT, SP, SL1, LG1, SL2, LG2, 7, 3, false>(base, tw, 1.f);
            pass4<false, NTT, SP, SL1, LG1, SL2, LG2, 7, 1, false>(base, tw, 1.f);
            pass2<false, NTT, SP, SL1, LG1, SL2, LG2, 7, 0, false>(base, tw, 1.f);
        } else if constexpr (LOGN == 6) {
            pass4<false, NTT, SP, SL1, LG1, SL2, LG2, 6, 4, false>(base, tw, 1.f);
            pass4<false, NTT, SP, SL1, LG1, SL2, LG2, 6, 2, false>(base, tw, 1.f);
            pass4<false, NTT, SP, SL1, LG1, SL2, LG2, 6, 0, false>(base, tw, 1.f);
        } else {
            pass4<false, NTT, SP, SL1, LG1, SL2, LG2, 5, 3, false>(base, tw, 1.f);
            pass4<false, NTT, SP, SL1, LG1, SL2, LG2, 5, 1, false>(base, tw, 1.f);
            pass2<false, NTT, SP, SL1, LG1, SL2, LG2, 5, 0, false>(base, tw, 1.f);
        }
    } else {
        if constexpr (LOGN == 7) {
            pass4<true, NTT, SP, SL1, LG1, SL2, LG2, 7, 0, false>(base, tw, 1.f);
            pass4<true, NTT, SP, SL1, LG1, SL2, LG2, 7, 2, false>(base, tw, 1.f);
            pass4<true, NTT, SP, SL1, LG1, SL2, LG2, 7, 4, false>(base, tw, 1.f);
            pass2<true, NTT, SP, SL1, LG1, SL2, LG2, 7, 6, true >(base, tw, scale);
        } else if constexpr (LOGN == 6) {
            pass4<true, NTT, SP, SL1, LG1, SL2, LG2, 6, 0, false>(base, tw, 1.f);
            pass4<true, NTT, SP, SL1, LG1, SL2, LG2, 6, 2, false>(base, tw, 1.f);
            pass4<true, NTT, SP, SL1, LG1, SL2, LG2, 6, 4, true >(base, tw, scale);
        } else {
            pass4<true, NTT, SP, SL1, LG1, SL2, LG2, 5, 0, false>(base, tw, 1.f);
            pass4<true, NTT, SP, SL1, LG1, SL2, LG2, 5, 2, false>(base, tw, 1.f);
            pass2<true, NTT, SP, SL1, LG1, SL2, LG2, 5, 4, true >(base, tw, scale);
        }
    }
}

__device__ __forceinline__ void apply_mux(float2& p0, float2& p1, float4 uA, float4 uB) {
    float2 o0, o1;
    o0.x = uA.x * p0.x - uA.y * p0.y + uA.z * p1.x - uA.w * p1.y;
    o0.y = uA.x * p0.y + uA.y * p0.x + uA.z * p1.y + uA.w * p1.x;
    o1.x = uB.x * p0.x - uB.y * p0.y + uB.z * p1.x - uB.w * p1.y;
    o1.y = uB.x * p0.y + uB.y * p0.x + uB.z * p1.y + uB.w * p1.x;
    p0 = o0; p1 = o1;
}

// ---------------- K0: precompute ----------------
__device__ __forceinline__ void writeU(float4* dst, float axf, float ayf, float azf) {
    double ax = axf, ay = ayf, az = azf;
    double r = sqrt(ax * ax + ay * ay + az * az + 1e-20);
    double cr = cos(r), sn = sin(r) / r;
    dst[0] = make_float4((float)cr, (float)(-az * sn), (float)(-ay * sn), (float)(-ax * sn));
    dst[1] = make_float4((float)(ay * sn), (float)(-ax * sn), (float)cr, (float)(az * sn));
}

__global__ void k0(const float* __restrict__ mux0, const float* __restrict__ mux1,
                   const float* __restrict__ mux2) {
    int idx = blockIdx.x * blockDim.x + threadIdx.x;   // 16384 threads
    if (idx < 64) {
        double ang = -2.0 * PI_D * (double)idx / 128.0;
        g_TW[idx] = make_float2((float)cos(ang), (float)sin(ang));
    }
    if (idx < 128) {
        int k = __brev((unsigned)idx) >> 25;
        g_NR[idx] = (int)(__brev((unsigned)((128 - k) & 127)) >> 25);
    }
    {
        int kxb = idx >> 7, kyb = idx & 127;
        int kx = __brev((unsigned)kxb) >> 25, ky = __brev((unsigned)kyb) >> 25;
        const float* c = mux0 + (kx * 128 + ky) * 3;
        writeU(&g_U0[idx * 2], c[0], c[1], c[2]);
    }
    {
        int cx = idx >> 13, cy = (idx >> 12) & 1, kxb = (idx >> 6) & 63, kyb = idx & 63;
        int kx = __brev((unsigned)kxb) >> 26, ky = __brev((unsigned)kyb) >> 26;
        const float* c = mux1 + (((cx * 2 + cy) * 64 + kx) * 64 + ky) * 3;
        writeU(&g_U1[idx * 2], c[0], c[1], c[2]);
    }
    if (idx < 4096) {
        int cx = idx >> 11, cy = (idx >> 10) & 1, kxb = (idx >> 5) & 31, kyb = idx & 31;
        int kx = __brev((unsigned)kxb) >> 27, ky = __brev((unsigned)kyb) >> 27;
        const float* c = mux2 + (((cx * 2 + cy) * 32 + kx) * 32 + ky) * 3;
        writeU(&g_U2[idx * 2], c[0], c[1], c[2]);
    }
}

// ---------------- P1: encode + y-FFT128 (Hermitian packed) ----------------
#define NT1 512
__global__ __launch_bounds__(NT1) void p1(const float* __restrict__ images) {
    __shared__ float2 z[128 * 33];
    __shared__ float2 tw[64];
    const int b = blockIdx.y, X0 = blockIdx.x * 32;
    for (int i = threadIdx.x; i < 64; i += NT1) tw[i] = g_TW[i];
    for (int idx = threadIdx.x; idx < 4096; idx += NT1) {
        int l = idx >> 7, y = idx & 127;
        float I = images[(b * 128 + X0 + l) * 128 + y];
        float sv, cv;
        sincosf(0.5f * (float)PI_D * I, &sv, &cv);
        z[y * 33 + l] = make_float2(cv * (1.0f / 128.0f), sv * (1.0f / 128.0f));
    }
    __syncthreads();
    fft_run<false, NT1, 33, 1, 5, 0, 0, 7>(z, tw, 1.f);
    for (int idx = threadIdx.x; idx < 4096; idx += NT1) {
        int l = idx >> 7, kb = idx & 127;
        float2 Z = z[kb * 33 + l];
        float2 Zn = z[g_NR[kb] * 33 + l];
        float2 C  = make_float2(0.5f * (Z.x + Zn.x), 0.5f * (Z.y - Zn.y));
        float2 Sf = make_float2(0.5f * (Z.y + Zn.y), 0.5f * (Zn.x - Z.x));
        int X = X0 + l;
        g_S[((b * 2 + 0) * 128 + X) * 128 + kb] = C;
        g_S[((b * 2 + 1) * 128 + X) * 128 + kb] = Sf;
    }
}

// ---------------- P2: x-FFT128 + mux0 + x-IFFT128 + x-FFT64(halves) ----------------
// fused middle: fwd stage0 + mux0 + inv stages 0&1 in one sweep (f-plane pairs per thread)
#define NT2 512
__global__ __launch_bounds__(NT2) void p2() {
    __shared__ float2 tile[2 * 128 * 16];
    __shared__ float2 tw[64];
    const int b = blockIdx.y, y0 = blockIdx.x * 16;
    for (int i = threadIdx.x; i < 64; i += NT2) tw[i] = g_TW[i];
    for (int idx = threadIdx.x; idx < 4096; idx += NT2) {
        int yl = idx & 15, X = (idx >> 4) & 127, f = idx >> 11;
        tile[f * 2048 + X * 16 + yl] = g_S[((b * 2 + f) * 128 + X) * 128 + y0 + yl];
    }
    __syncthreads();
    // fwd128 stages 6..1
    pass4<false, NT2, 16, 1, 4, 2048, 1, 7, 5, false>(tile, tw, 1.f);
    pass4<false, NT2, 16, 1, 4, 2048, 1, 7, 3, false>(tile, tw, 1.f);
    pass4<false, NT2, 16, 1, 4, 2048, 1, 7, 1, false>(tile, tw, 1.f);
    // fused: fwd s0 + mux0 + inv s0&1   (512 items, thread owns quad x both planes)
    for (int u = threadIdx.x; u < 512; u += NT2) {
        int yl = u & 15, v = u >> 4;                 // v in [0,32): quad base p = 4v
        float2* e0 = tile + v * 64 + yl;             // (4v)*16 + yl
        float2* e1 = e0 + 2048;
        float2 a0 = e0[0], b0 = e0[16], c0 = e0[32], d0 = e0[48];
        float2 a1 = e1[0], b1 = e1[16], c1 = e1[32], d1 = e1[48];
        // fwd stage 0 (w = 1)
        float2 A0 = f2add(a0, b0), A1 = f2sub(a0, b0), A2 = f2add(c0, d0), A3 = f2sub(c0, d0);
        float2 B0 = f2add(a1, b1), B1 = f2sub(a1, b1), B2 = f2add(c1, d1), B3 = f2sub(c1, d1);
        // mux0 at storage positions p = 4v+k, y = y0+yl
        int ub = ((v * 4) << 7) + y0 + yl;
        apply_mux(A0, B0, g_U0[ub * 2],             g_U0[ub * 2 + 1]);
        apply_mux(A1, B1, g_U0[(ub + 128) * 2],     g_U0[(ub + 128) * 2 + 1]);
        apply_mux(A2, B2, g_U0[(ub + 256) * 2],     g_U0[(ub + 256) * 2 + 1]);
        apply_mux(A3, B3, g_U0[(ub + 384) * 2],     g_U0[(ub + 384) * 2 + 1]);
        // inv stage 0 (w = 1)
        float2 P0 = f2add(A0, A1), P1 = f2sub(A0, A1), P2 = f2add(A2, A3), P3 = f2sub(A2, A3);
        float2 Q0 = f2add(B0, B1), Q1 = f2sub(B0, B1), Q2 = f2add(B2, B3), Q3 = f2sub(B2, B3);
        // inv stage 1: pair (0,2) w=1; pair (1,3) w = -i (conj applied)
        const float2 wm = make_float2(0.f, -1.f);
        float2 pq = cmulc(P3, wm), qq = cmulc(Q3, wm);
        e0[0]  = f2add(P0, P2);  e0[32] = f2sub(P0, P2);
        e0[16] = f2add(P1, pq);  e0[48] = f2sub(P1, pq);
        e1[0]  = f2add(Q0, Q2);  e1[32] = f2sub(Q0, Q2);
        e1[16] = f2add(Q1, qq);  e1[48] = f2sub(Q1, qq);
    }
    __syncthreads();
    // inv128 stages 2..6 (scale on last)
    pass4<true, NT2, 16, 1, 4, 2048, 1, 7, 2, false>(tile, tw, 1.f);
    pass4<true, NT2, 16, 1, 4, 2048, 1, 7, 4, false>(tile, tw, 1.f);
    pass2<true, NT2, 16, 1, 4, 2048, 1, 7, 6, true >(tile, tw, 1.0f / 128.0f);
    // fwd64 on x halves (both planes)
    fft_run<false, NT2, 16, 1, 4, 1024, 2, 6>(tile, tw, 1.f);
    for (int idx = threadIdx.x; idx < 4096; idx += NT2) {
        int yl = idx & 15, X = (idx >> 4) & 127, f = idx >> 11;
        g_S[((b * 2 + f) * 128 + X) * 128 + y0 + yl] = tile[f * 2048 + X * 16 + yl];
    }
}

// ---------------- P35: y-junction(+mux1 fused) + x-junction + y-junction(+mux2 fused)
//                   + final IFFT32s + measure + partial GEMV ----------------
#define NT3 1024
#define P35_SMEM (132096 + 512 + 8192 + 1280)
__global__ __launch_bounds__(NT3) void p35(const float* __restrict__ W) {
    extern __shared__ char sm[];
    float2* tile = (float2*)sm;                            // [2][64][129]
    float2* tw   = (float2*)(sm + 132096);
    float*  prob = (float*)(sm + 132096 + 512);            // 2048 f32
    float*  red  = (float*)(sm + 132096 + 512 + 8192);     // 32*10 f32
    const int b = blockIdx.y, xc1 = blockIdx.x;
    for (int i = threadIdx.x; i < 64; i += NT3) tw[i] = g_TW[i];
    for (int idx = threadIdx.x; idx < 16384; idx += NT3) {
        int Y = idx & 127, X = (idx >> 7) & 63, f = idx >> 13;
        tile[f * 8256 + X * 129 + Y] = g_S[((b * 2 + f) * 128 + xc1 * 64 + X) * 128 + Y];
    }
    __syncthreads();
    // y inv128
    fft_run<true, NT3, 1, 129, 7, 0, 0, 7>(tile, tw, 1.0f / 128.0f);
    // y fwd64 halves, stages 5..2
    pass4<false, NT3, 1, 129, 7, 64, 1, 6, 4, false>(tile, tw, 1.f);
    pass4<false, NT3, 1, 129, 7, 64, 1, 6, 2, false>(tile, tw, 1.f);
    // fused: y fwd64 stages 1&0 + mux1 (2048 items, thread owns quad x both planes)
    for (int u = threadIdx.x; u < 2048; u += NT3) {
        int X = u & 63, half = (u >> 6) & 1, v = u >> 7;   // v in [0,16): quad base Yb = 4v
        float2* e0 = tile + X * 129 + half * 64 + v * 4;
        float2* e1 = e0 + 8256;
        float2 a0 = e0[0], b0 = e0[1], c0 = e0[2], d0 = e0[3];
        float2 a1 = e1[0], b1 = e1[1], c1 = e1[2], d1 = e1[3];
        // fwd stages 1&0 at t=0: w0=1, w1=-i, w2=1
        const float2 wm = make_float2(0.f, -1.f);
        float2 ac0 = f2add(a0, c0), bd0 = f2add(b0, d0);
        float2 cP0 = f2sub(a0, c0), dP0 = cmul(f2sub(b0, d0), wm);
        float2 A0 = f2add(ac0, bd0), A1 = f2sub(ac0, bd0);
        float2 A2 = f2add(cP0, dP0), A3 = f2sub(cP0, dP0);
        float2 ac1 = f2add(a1, c1), bd1 = f2add(b1, d1);
        float2 cP1 = f2sub(a1, c1), dP1 = cmul(f2sub(b1, d1), wm);
        float2 B0 = f2add(ac1, bd1), B1 = f2sub(ac1, bd1);
        float2 B2 = f2add(cP1, dP1), B3 = f2sub(cP1, dP1);
        // mux1 at (xc1, yc1=half, X, Yb=4v+k)
        int ub = ((xc1 * 2 + half) << 12) + (X << 6) + v * 4;
        apply_mux(A0, B0, g_U1[ub * 2],           g_U1[ub * 2 + 1]);
        apply_mux(A1, B1, g_U1[(ub + 1) * 2],     g_U1[(ub + 1) * 2 + 1]);
        apply_mux(A2, B2, g_U1[(ub + 2) * 2],     g_U1[(ub + 2) * 2 + 1]);
        apply_mux(A3, B3, g_U1[(ub + 3) * 2],     g_U1[(ub + 3) * 2 + 1]);
        e0[0] = A0; e0[1] = A1; e0[2] = A2; e0[3] = A3;
        e1[0] = B0; e1[1] = B1; e1[2] = B2; e1[3] = B3;
    }
    __syncthreads();
    // x junction 64->32
    fft_run<true,  NT3, 129, 1, 7, 8256, 1, 6>(tile, tw, 1.0f / 64.0f);
    fft_run<false, NT3, 129, 1, 7, 4128, 2, 5>(tile, tw, 1.f);
    // y junction 64->32: inv64, then fwd32 stages 4..1
    fft_run<true, NT3, 1, 129, 7, 64, 1, 6>(tile, tw, 1.0f / 64.0f);
    pass4<false, NT3, 1, 129, 7, 32, 2, 5, 3, false>(tile, tw, 1.f);
    pass4<false, NT3, 1, 129, 7, 32, 2, 5, 1, false>(tile, tw, 1.f);
    // fused: y fwd32 stage 0 + mux2 (4096 items, thread owns pair x both planes)
    for (int u = threadIdx.x; u < 4096; u += NT3) {
        int X = u & 63, yseg = (u >> 6) & 3, m = u >> 8;   // m in [0,16): pair base
        float2* e0 = tile + X * 129 + yseg * 32 + m * 2;
        float2* e1 = e0 + 8256;
        float2 a0 = e0[0], b0 = e0[1];
        float2 a1 = e1[0], b1 = e1[1];
        float2 A0 = f2add(a0, b0), A1 = f2sub(a0, b0);
        float2 B0 = f2add(a1, b1), B1 = f2sub(a1, b1);
        int xc2 = X >> 5, yc2 = yseg & 1;
        int ub = ((xc2 * 2 + yc2) << 10) + ((X & 31) << 5) + m * 2;
        apply_mux(A0, B0, g_U2[ub * 2],       g_U2[ub * 2 + 1]);
        apply_mux(A1, B1, g_U2[(ub + 1) * 2], g_U2[(ub + 1) * 2 + 1]);
        e0[0] = A0; e0[1] = A1;
        e1[0] = B0; e1[1] = B1;
    }
    __syncthreads();
    // final iqft2d (32-point both axes)
    fft_run<true, NT3, 129, 1, 7, 4128, 2, 5>(tile, tw, 1.0f / 32.0f);
    fft_run<true, NT3, 1, 129, 7, 32,   2, 5>(tile, tw, 1.0f / 32.0f);
    // measurement: partial prob over (xc2, yc1, yc2)
    for (int idx = threadIdx.x; idx < 2048; idx += NT3) {
        int f = idx & 1, ya = (idx >> 1) & 31, xa = idx >> 6;
        float s = 0.f;
        #pragma unroll
        for (int xc2 = 0; xc2 < 2; ++xc2)
            #pragma unroll
            for (int yq = 0; yq < 4; ++yq) {
                float2 v = tile[f * 8256 + (xc2 * 32 + xa) * 129 + yq * 32 + ya];
                s += v.x * v.x + v.y * v.y;
            }
        prob[idx] = s;
    }
    __syncthreads();
    // partial GEMV
    float acc[10];
    #pragma unroll
    for (int c = 0; c < 10; ++c) acc[c] = 0.f;
    {
        int j0 = threadIdx.x * 2;
        float2 pv = *(const float2*)(prob + j0);
        #pragma unroll
        for (int c = 0; c < 10; ++c) {
            float2 wv = *(const float2*)(W + c * 2048 + j0);
            acc[c] = fmaf(pv.x, wv.x, fmaf(pv.y, wv.y, acc[c]));
        }
    }
    #pragma unroll
    for (int c = 0; c < 10; ++c)
        #pragma unroll
        for (int o = 16; o > 0; o >>= 1)
            acc[c] += __shfl_down_sync(0xffffffffu, acc[c], o);
    const int warp = threadIdx.x >> 5, lane = threadIdx.x & 31;
    if (lane == 0)
        #pragma unroll
        for (int c = 0; c < 10; ++c) red[warp * 10 + c] = acc[c];
    __syncthreads();
    if (threadIdx.x < 10) {
        float s = 0.f;
        #pragma unroll
        for (int w = 0; w < 32; ++w) s += red[w * 10 + threadIdx.x];
        g_part[(b * 2 + xc1) * 10 + threadIdx.x] = s;
    }
}

// ---------------- combine ----------------
__global__ void pc(const float* __restrict__ bias, float* __restrict__ out) {
    int i = blockIdx.x * blockDim.x + threadIdx.x;
    if (i < 5120) {
        int b = i / 10, c = i % 10;
        out[i] = bias[c] + g_part[(b * 2) * 10 + c] + g_part[(b * 2 + 1) * 10 + c];
    }
}

// ---------------- launch ----------------
extern "C" void kernel_launch(void* const* d_in, const int* in_sizes, int n_in,
                              void* d_out, int out_size) {
    const float* images = (const float*)d_in[0];
    const float* mux0 = (const float*)d_in[1];
    const float* mux1 = (const float*)d_in[2];
    const float* mux2 = (const float*)d_in[3];
    const float* W = (const float*)d_in[4];
    const float* bias = (const float*)d_in[5];
    float* out = (float*)d_out;
    (void)in_sizes; (void)n_in; (void)out_size;

    cudaFuncSetAttribute(p35, cudaFuncAttributeMaxDynamicSharedMemorySize, P35_SMEM);

    k0<<<64, 256>>>(mux0, mux1, mux2);
    p1<<<dim3(4, 512), NT1>>>(images);
    p2<<<dim3(8, 512), NT2>>>();
    p35<<<dim3(2, 512), NT3, P35_SMEM>>>(W);
    pc<<<10, 512>>>(bias, out);
}